// round 2
// baseline (speedup 1.0000x reference)
#include <cuda_runtime.h>

#define NBATCH 512
#define NROWS  256
#define NVECS  8
#define VEC    128
#define EPSV   1e-8f

// scratch: 1/max(||w[r,n]||, eps) for 256x8 sub-vectors
__device__ float g_inv_wn[NROWS * NVECS];

// One warp per (r, n): 128 elems = 32 lanes x float4
__global__ void wn_kernel(const float* __restrict__ w) {
    int g    = blockIdx.x * 8 + (threadIdx.x >> 5);   // 0..2047
    int lane = threadIdx.x & 31;
    int r = g >> 3, n = g & 7;
    const float4* wp = (const float4*)(w + (size_t)r * 1024 + n * 128);
    float4 v = wp[lane];
    float s = v.x * v.x + v.y * v.y + v.z * v.z + v.w * v.w;
#pragma unroll
    for (int o = 16; o; o >>= 1) s += __shfl_xor_sync(0xffffffffu, s, o);
    if (lane == 0) g_inv_wn[g] = 1.0f / fmaxf(sqrtf(s), EPSV);
}

// Block = 8 queries (one per warp) x 32 weight rows.
// Grid = (512/8) * (256/32) = 512 blocks, 256 threads.
__global__ __launch_bounds__(256) void nand_kernel(
    const float* __restrict__ q,
    const float* __restrict__ w,
    float* __restrict__ out)
{
    __shared__ float4 q_s[8 * 256];  // 8 rows x 1024 floats = 32 KB
    __shared__ float4 w_s[256];      // 1 row  x 1024 floats =  4 KB

    const int tid  = threadIdx.x;
    const int warp = tid >> 5;
    const int lane = tid & 31;
    const int bchunk = blockIdx.x >> 3;   // 0..63
    const int rchunk = blockIdx.x & 7;    // 0..7
    const int b0 = bchunk * 8;

    // ---- load 8 query rows (32 KB contiguous), coalesced float4 ----
    const float4* qg = (const float4*)(q + (size_t)b0 * 1024);
#pragma unroll
    for (int k = 0; k < 8; k++) q_s[tid + 256 * k] = qg[tid + 256 * k];
    __syncthreads();

    // ---- per-warp query sub-vector inverse norms (warp 'warp' owns b = b0+warp) ----
    float inv_qn[8];
#pragma unroll
    for (int n = 0; n < 8; n++) {
        float4 v = q_s[warp * 256 + n * 32 + lane];
        float s = fmaf(v.x, v.x, fmaf(v.y, v.y, fmaf(v.z, v.z, v.w * v.w)));
#pragma unroll
        for (int o = 16; o; o >>= 1) s += __shfl_xor_sync(0xffffffffu, s, o);
        inv_qn[n] = 1.0f / fmaxf(sqrtf(s), EPSV);
    }

    for (int row = 0; row < 32; row++) {
        const int r = rchunk * 32 + row;

        __syncthreads();  // all warps done reading previous w_s
        w_s[tid] = ((const float4*)(w + (size_t)r * 1024))[tid];
        __syncthreads();

        // ---- 8 dots for (b = b0+warp, r) ----
        float cs[8], ms[8];
#pragma unroll
        for (int n = 0; n < 8; n++) {
            float4 wv = w_s[n * 32 + lane];
            float4 qv = q_s[warp * 256 + n * 32 + lane];
            float s = fmaf(wv.x, qv.x, fmaf(wv.y, qv.y, fmaf(wv.z, qv.z, wv.w * qv.w)));
#pragma unroll
            for (int o = 16; o; o >>= 1) s += __shfl_xor_sync(0xffffffffu, s, o);
            float c = fmaxf(s * inv_qn[n] * g_inv_wn[r * 8 + n], 0.0f);
            cs[n] = c;
            ms[n] = 1.0f - c;
        }

        // ---- expansion: i = lane*8 + m, m = 0..7 ----
        // factor_n(i) = (i>>n)&1 ? (1-cs_n) : cs_n
        // bits 3..7 of i == bits 0..4 of lane -> shared "base"
        float base = ((lane >> 0) & 1 ? ms[3] : cs[3]);
        base *= ((lane >> 1) & 1 ? ms[4] : cs[4]);
        base *= ((lane >> 2) & 1 ? ms[5] : cs[5]);
        base *= ((lane >> 3) & 1 ? ms[6] : cs[6]);
        base *= ((lane >> 4) & 1 ? ms[7] : cs[7]);

        // 2^2 tree over bits 0,1 then bit 2
        float p0 = cs[0] * cs[1];
        float p1 = ms[0] * cs[1];
        float p2 = cs[0] * ms[1];
        float p3 = ms[0] * ms[1];
        float b2c = base * cs[2];
        float b2m = base * ms[2];

        float4 o0, o1;
        o0.x = b2c * p0;  // m=0: c0 c1 c2
        o0.y = b2c * p1;  // m=1: m0 c1 c2
        o0.z = b2c * p2;  // m=2: c0 m1 c2
        o0.w = b2c * p3;  // m=3: m0 m1 c2
        o1.x = b2m * p0;  // m=4
        o1.y = b2m * p1;  // m=5
        o1.z = b2m * p2;  // m=6
        o1.w = b2m * p3;  // m=7

        float4* op = (float4*)(out + ((size_t)(b0 + warp) * 256 + r) * 256 + lane * 8);
        op[0] = o0;
        op[1] = o1;
    }
}

extern "C" void kernel_launch(void* const* d_in, const int* in_sizes, int n_in,
                              void* d_out, int out_size) {
    const float* q = (const float*)d_in[0];   // 512 x 1024
    const float* w = (const float*)d_in[1];   // 256 x 1024
    float* out = (float*)d_out;               // 512 x 256 x 256

    wn_kernel<<<NROWS * NVECS / 8, 256>>>(w);
    nand_kernel<<<(NBATCH / 8) * (NROWS / 32), 256>>>(q, w, out);
}

// round 3
// speedup vs baseline: 1.3330x; 1.3330x over previous
#include <cuda_runtime.h>

#define EPSV 1e-8f

// ---- scratch (static __device__, no allocs) ----
__device__ __align__(16) float g_cs[512 * 256 * 8];   // cs[b][r][n], 4 MB
__device__ float g_inv_qn[512 * 8];
__device__ float g_inv_wn[256 * 8];

// ---------------------------------------------------------------------------
// Norms: one warp per (row, n). g in [0,6144): first 4096 = query, rest = weight.
// ---------------------------------------------------------------------------
__global__ void norm_kernel(const float* __restrict__ q, const float* __restrict__ w) {
    int g    = blockIdx.x * 8 + (threadIdx.x >> 5);
    int lane = threadIdx.x & 31;
    const float* src;
    float* dst;
    int idx;
    if (g < 4096) { src = q; dst = g_inv_qn; idx = g; }
    else          { src = w; dst = g_inv_wn; idx = g - 4096; }
    int row = idx >> 3, n = idx & 7;
    const float4* p = (const float4*)(src + (size_t)row * 1024 + n * 128);
    float4 v = p[lane];
    float s = fmaf(v.x, v.x, fmaf(v.y, v.y, fmaf(v.z, v.z, v.w * v.w)));
#pragma unroll
    for (int o = 16; o; o >>= 1) s += __shfl_xor_sync(0xffffffffu, s, o);
    if (lane == 0) dst[idx] = 1.0f / fmaxf(sqrtf(s), EPSV);
}

// ---------------------------------------------------------------------------
// Kernel A: cs[b][r][n] = relu(dot(q[b,n,:], w[r,n,:]) * inv_qn * inv_wn)
// Tile 32b x 32r, 256 threads (16x16), 2x2 register blocking, loop over n.
// Grid = 16 b-tiles * 8 r-tiles = 128 blocks.
// ---------------------------------------------------------------------------
__global__ __launch_bounds__(256) void cs_kernel(const float* __restrict__ q,
                                                 const float* __restrict__ w) {
    __shared__ float4 qs[32][33];
    __shared__ float4 ws[32][33];

    const int tid = threadIdx.x;
    const int tx = tid & 15, ty = tid >> 4;
    const int bt = blockIdx.x >> 3;   // 0..15
    const int rt = blockIdx.x & 7;    // 0..7
    const int b0 = bt * 32, r0 = rt * 32;

    const float4* q4 = (const float4*)q;
    const float4* w4 = (const float4*)w;

    for (int n = 0; n < 8; n++) {
        __syncthreads();
        // load 32x128-float q and w sub-tiles (1024 float4 each), coalesced
#pragma unroll
        for (int k = 0; k < 4; k++) {
            int idx = tid + 256 * k;
            int row = idx >> 5, col = idx & 31;
            qs[row][col] = q4[(size_t)(b0 + row) * 256 + n * 32 + col];
            ws[row][col] = w4[(size_t)(r0 + row) * 256 + n * 32 + col];
        }
        __syncthreads();

        float a00 = 0.f, a01 = 0.f, a10 = 0.f, a11 = 0.f;
#pragma unroll
        for (int k = 0; k < 32; k++) {
            float4 qa = qs[2 * ty + 0][k];
            float4 qb = qs[2 * ty + 1][k];
            float4 wa = ws[2 * tx + 0][k];
            float4 wb = ws[2 * tx + 1][k];
            a00 = fmaf(qa.x, wa.x, fmaf(qa.y, wa.y, fmaf(qa.z, wa.z, fmaf(qa.w, wa.w, a00))));
            a01 = fmaf(qa.x, wb.x, fmaf(qa.y, wb.y, fmaf(qa.z, wb.z, fmaf(qa.w, wb.w, a01))));
            a10 = fmaf(qb.x, wa.x, fmaf(qb.y, wa.y, fmaf(qb.z, wa.z, fmaf(qb.w, wa.w, a10))));
            a11 = fmaf(qb.x, wb.x, fmaf(qb.y, wb.y, fmaf(qb.z, wb.z, fmaf(qb.w, wb.w, a11))));
        }

        float iq0 = g_inv_qn[(b0 + 2 * ty + 0) * 8 + n];
        float iq1 = g_inv_qn[(b0 + 2 * ty + 1) * 8 + n];
        float iw0 = g_inv_wn[(r0 + 2 * tx + 0) * 8 + n];
        float iw1 = g_inv_wn[(r0 + 2 * tx + 1) * 8 + n];

        size_t base0 = ((size_t)(b0 + 2 * ty + 0) * 256 + (r0 + 2 * tx)) * 8 + n;
        size_t base1 = ((size_t)(b0 + 2 * ty + 1) * 256 + (r0 + 2 * tx)) * 8 + n;
        g_cs[base0]     = fmaxf(a00 * iq0 * iw0, 0.f);
        g_cs[base0 + 8] = fmaxf(a01 * iq0 * iw1, 0.f);
        g_cs[base1]     = fmaxf(a10 * iq1 * iw0, 0.f);
        g_cs[base1 + 8] = fmaxf(a11 * iq1 * iw1, 0.f);
    }
}

// ---------------------------------------------------------------------------
// Kernel B: pure streaming expansion. One warp per (b,r) pair.
// out[p][i], i = lane*8 + m; factor_n(i) = bit_n(i) ? (1-cs_n) : cs_n.
// Grid = 131072/8 = 16384 blocks of 256 threads; 1 KB contiguous per warp.
// ---------------------------------------------------------------------------
__global__ __launch_bounds__(256) void expand_kernel(float* __restrict__ out) {
    const int warp = threadIdx.x >> 5;
    const int lane = threadIdx.x & 31;
    const int p = blockIdx.x * 8 + warp;   // b*256 + r

    const float4* c4 = (const float4*)(g_cs + (size_t)p * 8);
    float4 cA = c4[0];   // uniform address -> broadcast
    float4 cB = c4[1];

    float cs0 = cA.x, cs1 = cA.y, cs2 = cA.z, cs3 = cA.w;
    float cs4 = cB.x, cs5 = cB.y, cs6 = cB.z, cs7 = cB.w;
    float ms0 = 1.f - cs0, ms1 = 1.f - cs1, ms2 = 1.f - cs2, ms3 = 1.f - cs3;
    float ms4 = 1.f - cs4, ms5 = 1.f - cs5, ms6 = 1.f - cs6, ms7 = 1.f - cs7;

    // bits 3..7 of i come from lane bits 0..4
    float base = ((lane >> 0) & 1 ? ms3 : cs3);
    base *= ((lane >> 1) & 1 ? ms4 : cs4);
    base *= ((lane >> 2) & 1 ? ms5 : cs5);
    base *= ((lane >> 3) & 1 ? ms6 : cs6);
    base *= ((lane >> 4) & 1 ? ms7 : cs7);

    float p0 = cs0 * cs1, p1 = ms0 * cs1, p2 = cs0 * ms1, p3 = ms0 * ms1;
    float b2c = base * cs2, b2m = base * ms2;

    float4 o0, o1;
    o0.x = b2c * p0;  o0.y = b2c * p1;  o0.z = b2c * p2;  o0.w = b2c * p3;
    o1.x = b2m * p0;  o1.y = b2m * p1;  o1.z = b2m * p2;  o1.w = b2m * p3;

    float4* op = (float4*)(out + (size_t)p * 256 + lane * 8);
    op[0] = o0;
    op[1] = o1;
}

extern "C" void kernel_launch(void* const* d_in, const int* in_sizes, int n_in,
                              void* d_out, int out_size) {
    const float* q = (const float*)d_in[0];   // 512 x 1024
    const float* w = (const float*)d_in[1];   // 256 x 1024
    float* out = (float*)d_out;               // 512 x 256 x 256

    norm_kernel<<<768, 256>>>(q, w);          // 6144 warps: 4096 q-norms + 2048 w-norms
    cs_kernel<<<128, 256>>>(q, w);
    expand_kernel<<<16384, 256>>>(out);
}